// round 15
// baseline (speedup 1.0000x reference)
#include <cuda_runtime.h>
#include <cuda_bf16.h>
#include <stdint.h>

// ---------------- problem constants ----------------
#define E_TOTAL   1600000
#define N_NODES   100000
#define NODE_DIM  64
#define EDGE_DIM  32
#define HID       128
#define OUT_DIM   64
#define HPRE_DIM  256          // [src-part 128 | tgt-part 128]

#define EPW       8            // edges per warp-tile
#define NTILES    (E_TOTAL / EPW)   // 200000
#define NT2       512
#define NW2       16

// ---------------- kernel2 smem byte layout ----------------
#define SO_W1EA   0                         // [32 k][128 j] f32        = 16384
#define SO_W2T    16384                     // [64 o][132] f32          = 33792
#define SO_MDUP   50176                     // 16 warps x [8 e][32 k] u64 = 32768
#define SO_HW     82944                     // 16 warps x [8 e][128 j] f32 = 65536
#define SO_B2     148480                    // 64 f32
#define SM2_BYTES 148736

#define W2T_STRIDE 132                      // f32 stride; 132 % 32 == 4 -> conflict-free LDS.128

typedef unsigned long long u64;

__device__ __forceinline__ u64 fma2(u64 a, u64 b, u64 c) {
    u64 d; asm("fma.rn.f32x2 %0, %1, %2, %3;" : "=l"(d) : "l"(a), "l"(b), "l"(c)); return d;
}
__device__ __forceinline__ u64 add2(u64 a, u64 b) {
    u64 d; asm("add.rn.f32x2 %0, %1, %2;" : "=l"(d) : "l"(a), "l"(b)); return d;
}
__device__ __forceinline__ u64 pack2(float lo, float hi) {
    u64 d; asm("mov.b64 %0, {%1, %2};" : "=l"(d) : "f"(lo), "f"(hi)); return d;
}
__device__ __forceinline__ float2 unpack2(u64 v) {
    float2 r; asm("mov.b64 {%0, %1}, %2;" : "=f"(r.x), "=f"(r.y) : "l"(v)); return r;
}

// Per-node precomputed partials:
// [n][0:128] = x[n] @ W1[0:64,:], [n][128:256] = x[n] @ W1[64:128,:]
__device__ float g_hpre[(size_t)N_NODES * HPRE_DIM];
__device__ int g_idx_is32;

__global__ void detect_idx_dtype_kernel(const unsigned int* __restrict__ a) {
    unsigned v = 0;
    for (int i = threadIdx.x; i < 2048; i += blockDim.x) v |= a[2 * i + 1];
    int any = __syncthreads_or(v != 0);
    if (threadIdx.x == 0) g_idx_is32 = any ? 1 : 0;
}

// ---------------- kernel 1: per-node precompute (unchanged, proven) ----------------
__global__ void __launch_bounds__(256, 1)
node_pre_kernel(const float* __restrict__ x, const float* __restrict__ W1)
{
    __shared__ float Wc[64 * 256];   // Wc[k][j]: j<128 -> W1[k][j], j>=128 -> W1[64+k][j-128]
    const int tid = threadIdx.x;
    for (int i = tid; i < 64 * 256; i += 256) {
        int k = i >> 8, j = i & 255;
        Wc[i] = (j < 128) ? W1[k * HID + j] : W1[(64 + k) * HID + (j - 128)];
    }
    __syncthreads();

    const int warp = tid >> 5, lane = tid & 31;
    const int gw = blockIdx.x * 8 + warp;
    const int nw = gridDim.x * 8;

    for (int n = gw; n < N_NODES; n += nw) {
        u64 acc0 = 0, acc1 = 0, acc2 = 0, acc3 = 0;
        const float4* xr = (const float4*)(x + (size_t)n * NODE_DIM);
#pragma unroll 4
        for (int c = 0; c < 16; c++) {
            float4 m = xr[c];
            float mv[4] = {m.x, m.y, m.z, m.w};
#pragma unroll
            for (int k = 0; k < 4; k++) {
                int kk = 4 * c + k;
                ulonglong2 w0 = *(const ulonglong2*)(Wc + kk * 256 + 4 * lane);
                ulonglong2 w1 = *(const ulonglong2*)(Wc + kk * 256 + 128 + 4 * lane);
                u64 pk = pack2(mv[k], mv[k]);
                acc0 = fma2(pk, w0.x, acc0);
                acc1 = fma2(pk, w0.y, acc1);
                acc2 = fma2(pk, w1.x, acc2);
                acc3 = fma2(pk, w1.y, acc3);
            }
        }
        ulonglong2 s0; s0.x = acc0; s0.y = acc1;
        ulonglong2 s1; s1.x = acc2; s1.y = acc3;
        *(ulonglong2*)(g_hpre + (size_t)n * HPRE_DIM + 4 * lane) = s0;
        *(ulonglong2*)(g_hpre + (size_t)n * HPRE_DIM + 128 + 4 * lane) = s1;
    }
}

// ---------------- kernel 2: zero-pack layers; layer 2 split in two 4-edge passes ----------------
__global__ void __launch_bounds__(NT2, 1)
edge_kernel(const float* __restrict__ ea,
            const float* __restrict__ W1,
            const float* __restrict__ b1,
            const float* __restrict__ W2,
            const float* __restrict__ b2,
            const void*  __restrict__ eidx,
            float* __restrict__ out)
{
    extern __shared__ __align__(1024) char smem[];
    float* W1ea = (float*)(smem + SO_W1EA);      // [32 k][128 j]
    float* W2T  = (float*)(smem + SO_W2T);       // [64 o][132], W2T[o][k] = W2[k][o]
    float* b2s  = (float*)(smem + SO_B2);

    const int tid  = threadIdx.x;
    const int warp = tid >> 5;
    const int lane = tid & 31;

    u64*   mdup = (u64*)(smem + SO_MDUP) + warp * (EPW * EDGE_DIM);   // [8 e][32 k], (m,m)
    float* hw   = (float*)(smem + SO_HW) + warp * (EPW * HID);        // [8 e][128 j] plain

    // ---- stage W1 rows 128..159 as-is ----
    for (int i = tid; i < EDGE_DIM * HID; i += NT2) W1ea[i] = W1[128 * HID + i];
    // ---- stage W2 transposed: W2T[o][k] = W2[k][o] ----
    for (int i = tid; i < HID * OUT_DIM; i += NT2) {
        int k = i >> 6, o = i & 63;
        W2T[o * W2T_STRIDE + k] = W2[i];
    }
    for (int i = tid; i < OUT_DIM; i += NT2) b2s[i] = b2[i];
    __syncthreads();

    const int is32 = g_idx_is32;
    const int* e32 = (const int*)eidx;
    const long long* e64 = (const long long*)eidx;

    // biases: j-quad for this lane (acc[e][0] = j {4L,4L+1}, acc[e][1] = j {4L+2,4L+3})
    float4 b1f = *(const float4*)(b1 + 4 * lane);
    const u64 b1q0 = pack2(b1f.x, b1f.y);
    const u64 b1q1 = pack2(b1f.z, b1f.w);
    const u64 b2q0 = pack2(b2s[lane], 0.0f);          // folded into layer-2 init
    const u64 b2q1 = pack2(b2s[lane + 32], 0.0f);

    const int gwarp = blockIdx.x * NW2 + warp;
    const int wstride = gridDim.x * NW2;

    for (int t = gwarp; t < NTILES; t += wstride) {
        const int ebase = t * EPW;

        // ---- edge indices: lanes 0..7 load, shfl ----
        int sv = 0, tv = 0;
        if (lane < EPW) {
            int e = ebase + lane;
            if (is32) { sv = e32[e]; tv = e32[E_TOTAL + e]; }
            else      { sv = (int)e64[e]; tv = (int)e64[E_TOTAL + e]; }
        }

        // ---- stage edge_attr DUPLICATED: mdup[e][k] = (m,m) ----
#pragma unroll
        for (int p = 0; p < 2; p++) {
            int i = lane + 32 * p;
            int e = i >> 3, q = i & 7;
            float4 v = *(const float4*)(ea + (size_t)(ebase + e) * EDGE_DIM + 4 * q);
            ulonglong2 d0, d1;
            d0.x = pack2(v.x, v.x); d0.y = pack2(v.y, v.y);
            d1.x = pack2(v.z, v.z); d1.y = pack2(v.w, v.w);
            *(ulonglong2*)(mdup + e * EDGE_DIM + 4 * q) = d0;
            *(ulonglong2*)(mdup + e * EDGE_DIM + 4 * q + 2) = d1;
        }
        __syncwarp();

        // ---- layer 1 init: b1 + hpre_src + hpre_tgt (j-pairs, zero packs) ----
        u64 acc[EPW][2];
#pragma unroll
        for (int e = 0; e < EPW; e++) {
            int se = __shfl_sync(0xffffffffu, sv, e);
            int te = __shfl_sync(0xffffffffu, tv, e);
            ulonglong2 hs = *(const ulonglong2*)(g_hpre + (size_t)se * HPRE_DIM + 4 * lane);
            ulonglong2 ht = *(const ulonglong2*)(g_hpre + (size_t)te * HPRE_DIM + 128 + 4 * lane);
            acc[e][0] = add2(add2(b1q0, hs.x), ht.x);
            acc[e][1] = add2(add2(b1q1, hs.y), ht.y);
        }

        // ---- layer 1 GEMM: ea @ W1[128:160,:], zero packs ----
#pragma unroll 2
        for (int c = 0; c < EDGE_DIM / 4; c++) {       // 8 chunks of 4 k
            ulonglong2 wq[4];                           // wq[k] = W1[k][4L..4L+3] as 2 j-pairs
#pragma unroll
            for (int k = 0; k < 4; k++)
                wq[k] = *(const ulonglong2*)(W1ea + (4 * c + k) * HID + 4 * lane);
#pragma unroll
            for (int e = 0; e < EPW; e++) {
                ulonglong2 m0 = *(const ulonglong2*)(mdup + e * EDGE_DIM + 4 * c);      // k=4c,4c+1
                ulonglong2 m1 = *(const ulonglong2*)(mdup + e * EDGE_DIM + 4 * c + 2);  // k=4c+2,4c+3
                acc[e][0] = fma2(m0.x, wq[0].x, acc[e][0]);
                acc[e][1] = fma2(m0.x, wq[0].y, acc[e][1]);
                acc[e][0] = fma2(m0.y, wq[1].x, acc[e][0]);
                acc[e][1] = fma2(m0.y, wq[1].y, acc[e][1]);
                acc[e][0] = fma2(m1.x, wq[2].x, acc[e][0]);
                acc[e][1] = fma2(m1.x, wq[2].y, acc[e][1]);
                acc[e][0] = fma2(m1.y, wq[3].x, acc[e][0]);
                acc[e][1] = fma2(m1.y, wq[3].y, acc[e][1]);
            }
        }

        // ---- layer 1 epilogue: relu + plain f32 j-quad store (STS.128, conflict-free) ----
#pragma unroll
        for (int e = 0; e < EPW; e++) {
            float2 p0 = unpack2(acc[e][0]);
            float2 p1 = unpack2(acc[e][1]);
            float4 hv;
            hv.x = fmaxf(p0.x, 0.0f); hv.y = fmaxf(p0.y, 0.0f);
            hv.z = fmaxf(p1.x, 0.0f); hv.w = fmaxf(p1.y, 0.0f);
            *(float4*)(hw + e * HID + 4 * lane) = hv;
        }
        __syncwarp();

        // ---- layer 2: K-paired f32x2, zero packs; TWO PASSES of 4 edges (16-reg acc) ----
        // lane covers o = lane and lane+32; acc halves = k-parity partials; b2 folded in.
#pragma unroll
        for (int hb = 0; hb < 2; hb++) {
            const int e0 = hb * 4;
            u64 a2[4][2];
#pragma unroll
            for (int e = 0; e < 4; e++) { a2[e][0] = b2q0; a2[e][1] = b2q1; }

#pragma unroll 4
            for (int c = 0; c < HID / 4; c++) {        // 32 chunks of 4 k
                ulonglong2 w0 = *(const ulonglong2*)(W2T + lane * W2T_STRIDE + 4 * c);
                ulonglong2 w1 = *(const ulonglong2*)(W2T + (lane + 32) * W2T_STRIDE + 4 * c);
#pragma unroll
                for (int e = 0; e < 4; e++) {
                    ulonglong2 h2 = *(const ulonglong2*)(hw + (e0 + e) * HID + 4 * c);  // broadcast
                    a2[e][0] = fma2(h2.x, w0.x, a2[e][0]);
                    a2[e][0] = fma2(h2.y, w0.y, a2[e][0]);
                    a2[e][1] = fma2(h2.x, w1.x, a2[e][1]);
                    a2[e][1] = fma2(h2.y, w1.y, a2[e][1]);
                }
            }

            // ---- fold k-parity halves + coalesced stores ----
#pragma unroll
            for (int e = 0; e < 4; e++) {
                float2 q0 = unpack2(a2[e][0]);
                float2 q1 = unpack2(a2[e][1]);
                size_t ob = (size_t)(ebase + e0 + e) * OUT_DIM;
                out[ob + lane]      = q0.x + q0.y;
                out[ob + lane + 32] = q1.x + q1.y;
            }
        }
        __syncwarp();   // before mdup/hw reuse next tile
    }
}

extern "C" void kernel_launch(void* const* d_in, const int* in_sizes, int n_in,
                              void* d_out, int out_size)
{
    const float* x  = (const float*)d_in[0];
    const float* ea = (const float*)d_in[1];
    const float* W1 = (const float*)d_in[2];
    const float* b1 = (const float*)d_in[3];
    const float* W2 = (const float*)d_in[4];
    const float* b2 = (const float*)d_in[5];
    const void*  ei = d_in[6];
    float* out = (float*)d_out;

    cudaFuncSetAttribute(edge_kernel,
                         cudaFuncAttributeMaxDynamicSharedMemorySize, SM2_BYTES);

    detect_idx_dtype_kernel<<<1, 256>>>((const unsigned int*)ei);
    node_pre_kernel<<<1480, 256>>>(x, W1);
    edge_kernel<<<1480, NT2, SM2_BYTES>>>(ea, W1, b1, W2, b2, ei, out);
}

// round 16
// speedup vs baseline: 1.5415x; 1.5415x over previous
#include <cuda_runtime.h>
#include <cuda_bf16.h>
#include <stdint.h>

// ---------------- problem constants ----------------
#define E_TOTAL   1600000
#define N_NODES   100000
#define NODE_DIM  64
#define EDGE_DIM  32
#define HID       128
#define OUT_DIM   64
#define HPRE_DIM  256          // [src-part 128 | tgt-part 128]

#define TPW       16           // edges per warp-tile (one m16 MMA tile)
#define NTILES16  (E_TOTAL / TPW)   // 100000
#define NT2       384
#define NW2       12

// ---------------- kernel2 smem layout (word = u32) ----------------
// h / W2 packed as bf16x2 over k: word w holds (k=2w lower, k=2w+1 upper).
// Row stride 68 words (64 + 4 pad) -> all MMA fragment LDS are conflict-free.
#define ROWW      68
#define SO_W1EA   0                          // [32 k][128 j] f32            = 16384
#define SO_W2PH   16384                      // u32 [64 n][68]               = 17408
#define SO_W2PL   33792                      // u32 [64 n][68]               = 17408
#define SO_MW     51200                      // 12 w x [16 e][32 k] f32      = 24576
#define SO_HPH    75776                      // 12 w x [16 e][68] u32        = 52224
#define SO_HPL    128000                     // 12 w x [16 e][68] u32        = 52224
#define SO_B2     180224                     // 64 f32                       = 256
#define SM2_BYTES 180480

typedef unsigned long long u64;

__device__ __forceinline__ u64 fma2(u64 a, u64 b, u64 c) {
    u64 d; asm("fma.rn.f32x2 %0, %1, %2, %3;" : "=l"(d) : "l"(a), "l"(b), "l"(c)); return d;
}
__device__ __forceinline__ u64 add2(u64 a, u64 b) {
    u64 d; asm("add.rn.f32x2 %0, %1, %2;" : "=l"(d) : "l"(a), "l"(b)); return d;
}
__device__ __forceinline__ u64 pack2(float lo, float hi) {
    u64 d; asm("mov.b64 %0, {%1, %2};" : "=l"(d) : "f"(lo), "f"(hi)); return d;
}
__device__ __forceinline__ float2 unpack2(u64 v) {
    float2 r; asm("mov.b64 {%0, %1}, %2;" : "=f"(r.x), "=f"(r.y) : "l"(v)); return r;
}
// packed bf16x2: lower half <- lo_f32, upper half <- hi_f32
__device__ __forceinline__ uint32_t packbf2(float lo, float hi) {
    uint32_t d; asm("cvt.rn.bf16x2.f32 %0, %1, %2;" : "=r"(d) : "f"(hi), "f"(lo)); return d;
}
__device__ __forceinline__ float bf_lo(uint32_t p) { return __uint_as_float(p << 16); }
__device__ __forceinline__ float bf_hi(uint32_t p) { return __uint_as_float(p & 0xffff0000u); }

__device__ __forceinline__ void mma_bf16(float* c, const uint32_t* a, const uint32_t* b) {
    asm("mma.sync.aligned.m16n8k16.row.col.f32.bf16.bf16.f32 "
        "{%0,%1,%2,%3}, {%4,%5,%6,%7}, {%8,%9}, {%0,%1,%2,%3};"
        : "+f"(c[0]), "+f"(c[1]), "+f"(c[2]), "+f"(c[3])
        : "r"(a[0]), "r"(a[1]), "r"(a[2]), "r"(a[3]), "r"(b[0]), "r"(b[1]));
}

// Per-node precomputed partials:
// [n][0:128] = x[n] @ W1[0:64,:], [n][128:256] = x[n] @ W1[64:128,:]
__device__ float g_hpre[(size_t)N_NODES * HPRE_DIM];
__device__ int g_idx_is32;

__global__ void detect_idx_dtype_kernel(const unsigned int* __restrict__ a) {
    unsigned v = 0;
    for (int i = threadIdx.x; i < 2048; i += blockDim.x) v |= a[2 * i + 1];
    int any = __syncthreads_or(v != 0);
    if (threadIdx.x == 0) g_idx_is32 = any ? 1 : 0;
}

// ---------------- kernel 1: per-node precompute (unchanged, proven) ----------------
__global__ void __launch_bounds__(256, 1)
node_pre_kernel(const float* __restrict__ x, const float* __restrict__ W1)
{
    __shared__ float Wc[64 * 256];
    const int tid = threadIdx.x;
    for (int i = tid; i < 64 * 256; i += 256) {
        int k = i >> 8, j = i & 255;
        Wc[i] = (j < 128) ? W1[k * HID + j] : W1[(64 + k) * HID + (j - 128)];
    }
    __syncthreads();

    const int warp = tid >> 5, lane = tid & 31;
    const int gw = blockIdx.x * 8 + warp;
    const int nw = gridDim.x * 8;

    for (int n = gw; n < N_NODES; n += nw) {
        u64 acc0 = 0, acc1 = 0, acc2 = 0, acc3 = 0;
        const float4* xr = (const float4*)(x + (size_t)n * NODE_DIM);
#pragma unroll 4
        for (int c = 0; c < 16; c++) {
            float4 m = xr[c];
            float mv[4] = {m.x, m.y, m.z, m.w};
#pragma unroll
            for (int k = 0; k < 4; k++) {
                int kk = 4 * c + k;
                ulonglong2 w0 = *(const ulonglong2*)(Wc + kk * 256 + 4 * lane);
                ulonglong2 w1 = *(const ulonglong2*)(Wc + kk * 256 + 128 + 4 * lane);
                u64 pk = pack2(mv[k], mv[k]);
                acc0 = fma2(pk, w0.x, acc0);
                acc1 = fma2(pk, w0.y, acc1);
                acc2 = fma2(pk, w1.x, acc2);
                acc3 = fma2(pk, w1.y, acc3);
            }
        }
        ulonglong2 s0; s0.x = acc0; s0.y = acc1;
        ulonglong2 s1; s1.x = acc2; s1.y = acc3;
        *(ulonglong2*)(g_hpre + (size_t)n * HPRE_DIM + 4 * lane) = s0;
        *(ulonglong2*)(g_hpre + (size_t)n * HPRE_DIM + 128 + 4 * lane) = s1;
    }
}

// ---------------- kernel 2: scalar layer 1 + split-bf16 HMMA layer 2 ----------------
__global__ void __launch_bounds__(NT2, 1)
edge_kernel(const float* __restrict__ ea,
            const float* __restrict__ W1,
            const float* __restrict__ b1,
            const float* __restrict__ W2,
            const float* __restrict__ b2,
            const void*  __restrict__ eidx,
            float* __restrict__ out)
{
    extern __shared__ __align__(1024) char smem[];
    float*    W1ea = (float*)(smem + SO_W1EA);     // [32 k][128 j]
    uint32_t* W2ph = (uint32_t*)(smem + SO_W2PH);  // [64 n][68] bf16x2-k hi
    uint32_t* W2pl = (uint32_t*)(smem + SO_W2PL);  // [64 n][68] bf16x2-k lo
    float*    b2s  = (float*)(smem + SO_B2);

    const int tid  = threadIdx.x;
    const int warp = tid >> 5;
    const int lane = tid & 31;
    const int g    = lane >> 2;       // MMA group id 0..7
    const int tg   = lane & 3;        // MMA thread-in-group 0..3

    float*    mw  = (float*)(smem + SO_MW)  + warp * (TPW * EDGE_DIM);   // [16 e][32 k]
    uint32_t* hph = (uint32_t*)(smem + SO_HPH) + warp * (TPW * ROWW);    // [16 e][68]
    uint32_t* hpl = (uint32_t*)(smem + SO_HPL) + warp * (TPW * ROWW);

    // ---- stage W1 rows 128..159 as-is ----
    for (int i = tid; i < EDGE_DIM * HID; i += NT2) W1ea[i] = W1[128 * HID + i];
    // ---- stage W2 as bf16x2-over-k, hi/lo split: W2p[n][w] = (W2[2w][n], W2[2w+1][n]) ----
    for (int i = tid; i < OUT_DIM * (HID / 2); i += NT2) {
        int n = i >> 6, w = i & 63;
        float f0 = W2[(2 * w) * OUT_DIM + n];
        float f1 = W2[(2 * w + 1) * OUT_DIM + n];
        uint32_t hi = packbf2(f0, f1);
        float l0 = f0 - bf_lo(hi);
        float l1 = f1 - bf_hi(hi);
        W2ph[n * ROWW + w] = hi;
        W2pl[n * ROWW + w] = packbf2(l0, l1);
    }
    for (int i = tid; i < OUT_DIM; i += NT2) b2s[i] = b2[i];
    __syncthreads();

    const int is32 = g_idx_is32;
    const int* e32 = (const int*)eidx;
    const long long* e64 = (const long long*)eidx;

    // layer-1 biases: j-quad for this lane
    float4 b1f = *(const float4*)(b1 + 4 * lane);
    const u64 b1q0 = pack2(b1f.x, b1f.y);
    const u64 b1q1 = pack2(b1f.z, b1f.w);

    const int gwarp = blockIdx.x * NW2 + warp;
    const int wstride = gridDim.x * NW2;

    for (int t = gwarp; t < NTILES16; t += wstride) {
        const int ebase = t * TPW;

        // ---- edge indices for 16 edges: lanes 0..15 load, shfl ----
        int sv = 0, tv = 0;
        if (lane < TPW) {
            int e = ebase + lane;
            if (is32) { sv = e32[e]; tv = e32[E_TOTAL + e]; }
            else      { sv = (int)e64[e]; tv = (int)e64[E_TOTAL + e]; }
        }

        // ---- stage edge_attr: 16 e x 32 k = 128 float4, 4 per lane ----
#pragma unroll
        for (int p = 0; p < 4; p++) {
            int i = lane + 32 * p;
            int e = i >> 3, q = i & 7;
            float4 v = *(const float4*)(ea + (size_t)(ebase + e) * EDGE_DIM + 4 * q);
            *(float4*)(mw + e * EDGE_DIM + 4 * q) = v;
        }
        __syncwarp();

        // ---- layer 1: two passes of 8 edges (R6-proven scalar form) ----
#pragma unroll
        for (int hp = 0; hp < 2; hp++) {
            const int e0 = hp * 8;
            u64 acc[8][2];
#pragma unroll
            for (int e = 0; e < 8; e++) {
                int se = __shfl_sync(0xffffffffu, sv, e0 + e);
                int te = __shfl_sync(0xffffffffu, tv, e0 + e);
                ulonglong2 hs = *(const ulonglong2*)(g_hpre + (size_t)se * HPRE_DIM + 4 * lane);
                ulonglong2 ht = *(const ulonglong2*)(g_hpre + (size_t)te * HPRE_DIM + 128 + 4 * lane);
                acc[e][0] = add2(add2(b1q0, hs.x), ht.x);
                acc[e][1] = add2(add2(b1q1, hs.y), ht.y);
            }

#pragma unroll 2
            for (int c = 0; c < EDGE_DIM / 4; c++) {   // 8 chunks of 4 k
                ulonglong2 wq[4];
#pragma unroll
                for (int k = 0; k < 4; k++)
                    wq[k] = *(const ulonglong2*)(W1ea + (4 * c + k) * HID + 4 * lane);
#pragma unroll
                for (int e = 0; e < 8; e++) {
                    float4 m4 = *(const float4*)(mw + (e0 + e) * EDGE_DIM + 4 * c);  // broadcast
                    float mv[4] = {m4.x, m4.y, m4.z, m4.w};
#pragma unroll
                    for (int k = 0; k < 4; k++) {
                        u64 pk = pack2(mv[k], mv[k]);
                        acc[e][0] = fma2(pk, wq[k].x, acc[e][0]);
                        acc[e][1] = fma2(pk, wq[k].y, acc[e][1]);
                    }
                }
            }

            // ---- epilogue: relu + bf16 hi/lo split, STS.64 at word 2*lane ----
#pragma unroll
            for (int e = 0; e < 8; e++) {
                float2 p0 = unpack2(acc[e][0]);
                float2 p1 = unpack2(acc[e][1]);
                float r0 = fmaxf(p0.x, 0.0f), r1 = fmaxf(p0.y, 0.0f);
                float r2 = fmaxf(p1.x, 0.0f), r3 = fmaxf(p1.y, 0.0f);
                uint32_t h0 = packbf2(r0, r1);            // k-pair (4L, 4L+1)
                uint32_t h1 = packbf2(r2, r3);            // k-pair (4L+2, 4L+3)
                uint32_t l0 = packbf2(r0 - bf_lo(h0), r1 - bf_hi(h0));
                uint32_t l1 = packbf2(r2 - bf_lo(h1), r3 - bf_hi(h1));
                int row = (e0 + e) * ROWW + 2 * lane;
                *(u64*)(hph + row) = ((u64)h1 << 32) | h0;
                *(u64*)(hpl + row) = ((u64)l1 << 32) | l0;
            }
        }
        __syncwarp();

        // ---- layer 2: m16n8k16 bf16 MMA, 3-term split (hi*hi + hi*lo + lo*hi) ----
        float acc2[8][4];
#pragma unroll
        for (int n0 = 0; n0 < 8; n0++)
#pragma unroll
            for (int r = 0; r < 4; r++) acc2[n0][r] = 0.0f;

#pragma unroll
        for (int kt = 0; kt < 8; kt++) {               // 8 k-tiles of 16
            const int wb = kt * 8 + tg;
            uint32_t ahi[4], alo[4];
            ahi[0] = hph[g * ROWW + wb];
            ahi[1] = hph[(g + 8) * ROWW + wb];
            ahi[2] = hph[g * ROWW + wb + 4];
            ahi[3] = hph[(g + 8) * ROWW + wb + 4];
            alo[0] = hpl[g * ROWW + wb];
            alo[1] = hpl[(g + 8) * ROWW + wb];
            alo[2] = hpl[g * ROWW + wb + 4];
            alo[3] = hpl[(g + 8) * ROWW + wb + 4];
#pragma unroll
            for (int n0 = 0; n0 < 8; n0++) {
                uint32_t bh[2], bl[2];
                bh[0] = W2ph[(n0 * 8 + g) * ROWW + wb];
                bh[1] = W2ph[(n0 * 8 + g) * ROWW + wb + 4];
                bl[0] = W2pl[(n0 * 8 + g) * ROWW + wb];
                bl[1] = W2pl[(n0 * 8 + g) * ROWW + wb + 4];
                mma_bf16(acc2[n0], ahi, bh);
                mma_bf16(acc2[n0], ahi, bl);
                mma_bf16(acc2[n0], alo, bh);
            }
        }

        // ---- epilogue: bias + stores (c0=(g,2tg), c1=(g,2tg+1), c2/c3 = row g+8) ----
#pragma unroll
        for (int n0 = 0; n0 < 8; n0++) {
            int col = n0 * 8 + 2 * tg;
            float2 bb = *(const float2*)(b2s + col);
            float2 v0, v1;
            v0.x = acc2[n0][0] + bb.x; v0.y = acc2[n0][1] + bb.y;
            v1.x = acc2[n0][2] + bb.x; v1.y = acc2[n0][3] + bb.y;
            *(float2*)(out + (size_t)(ebase + g) * OUT_DIM + col) = v0;
            *(float2*)(out + (size_t)(ebase + g + 8) * OUT_DIM + col) = v1;
        }
        __syncwarp();   // before mw/hph/hpl reuse next tile
    }
}

extern "C" void kernel_launch(void* const* d_in, const int* in_sizes, int n_in,
                              void* d_out, int out_size)
{
    const float* x  = (const float*)d_in[0];
    const float* ea = (const float*)d_in[1];
    const float* W1 = (const float*)d_in[2];
    const float* b1 = (const float*)d_in[3];
    const float* W2 = (const float*)d_in[4];
    const float* b2 = (const float*)d_in[5];
    const void*  ei = d_in[6];
    float* out = (float*)d_out;

    cudaFuncSetAttribute(edge_kernel,
                         cudaFuncAttributeMaxDynamicSharedMemorySize, SM2_BYTES);

    detect_idx_dtype_kernel<<<1, 256>>>((const unsigned int*)ei);
    node_pre_kernel<<<1480, 256>>>(x, W1);
    edge_kernel<<<1480, NT2, SM2_BYTES>>>(ea, W1, b1, W2, b2, ei, out);
}